// round 4
// baseline (speedup 1.0000x reference)
#include <cuda_runtime.h>
#include <math_constants.h>

static constexpr int K  = 1024;
static constexpr int D  = 64;
static constexpr int C  = 32;
static constexpr int NT = 256;       // threads per CTA
static constexpr int NW = NT / 32;   // 8 warps

__global__ __launch_bounds__(NT) void nw_attn_fused(
    const float* __restrict__ x,
    const float* __restrict__ keys,
    const float* __restrict__ values,
    const float* __restrict__ gamma,
    float* __restrict__ out)
{
    __shared__ float s_m[NW];
    __shared__ float s_zz[NW];
    __shared__ float s_acc[NW][C];

    const int b    = blockIdx.x;
    const int tid  = threadIdx.x;
    const int lane = tid & 31;
    const int warp = tid >> 5;

    const float g = gamma[0];

    // key-scoring lane map: 4 lanes per key, 8 keys per warp-iter
    const int l4 = lane & 3;               // 16-float dim chunk
    const int kw = lane >> 2;              // key slot 0..7

    const float* xb = x + (size_t)b * D + l4 * 16;
    const float4 xq0 = *reinterpret_cast<const float4*>(xb + 0);
    const float4 xq1 = *reinterpret_cast<const float4*>(xb + 4);
    const float4 xq2 = *reinterpret_cast<const float4*>(xb + 8);
    const float4 xq3 = *reinterpret_cast<const float4*>(xb + 12);

    const float* kb = keys   + (size_t)b * K * D;
    const float* vb = values + (size_t)b * K * C;

    // value-accumulation lane map: 4 keys x 8 channel-quads per instruction
    const int vk    = lane >> 3;           // value key slot 0..3
    const int cq    = (lane & 7) * 4;      // channel offset (fixed per lane)
    const int wsrc0 = vk * 4;              // lane holding w of key slot vk
    const int wsrc1 = 16 + vk * 4;         // lane holding w of key slot vk+4

    float  m   = -CUDART_INF_F;            // warp-uniform running max
    float  Zp  = 0.f;                      // partial Z (l4==0 lanes only)
    float4 acc = make_float4(0.f, 0.f, 0.f, 0.f);

    #pragma unroll 2
    for (int k0 = warp * 8; k0 < K; k0 += NW * 8) {   // 16 iters/warp
        // ---- score 8 keys ----
        const int key = k0 + kw;
        const float4* p = reinterpret_cast<const float4*>(
                              kb + (size_t)key * D + l4 * 16);
        const float4 a0 = __ldcs(p + 0);
        const float4 a1 = __ldcs(p + 1);
        const float4 a2 = __ldcs(p + 2);
        const float4 a3 = __ldcs(p + 3);

        float d, ss;
        d = xq0.x - a0.x; ss  = d * d;
        d = xq0.y - a0.y; ss = fmaf(d, d, ss);
        d = xq0.z - a0.z; ss = fmaf(d, d, ss);
        d = xq0.w - a0.w; ss = fmaf(d, d, ss);
        d = xq1.x - a1.x; ss = fmaf(d, d, ss);
        d = xq1.y - a1.y; ss = fmaf(d, d, ss);
        d = xq1.z - a1.z; ss = fmaf(d, d, ss);
        d = xq1.w - a1.w; ss = fmaf(d, d, ss);
        d = xq2.x - a2.x; ss = fmaf(d, d, ss);
        d = xq2.y - a2.y; ss = fmaf(d, d, ss);
        d = xq2.z - a2.z; ss = fmaf(d, d, ss);
        d = xq2.w - a2.w; ss = fmaf(d, d, ss);
        d = xq3.x - a3.x; ss = fmaf(d, d, ss);
        d = xq3.y - a3.y; ss = fmaf(d, d, ss);
        d = xq3.z - a3.z; ss = fmaf(d, d, ss);
        d = xq3.w - a3.w; ss = fmaf(d, d, ss);

        ss += __shfl_xor_sync(0xffffffffu, ss, 1);
        ss += __shfl_xor_sync(0xffffffffu, ss, 2);
        const float s = -g * ss;           // all 4 lanes of slot kw hold s

        // ---- warp-uniform chunk max + online rescale ----
        float cm = s;
        cm = fmaxf(cm, __shfl_xor_sync(0xffffffffu, cm, 4));
        cm = fmaxf(cm, __shfl_xor_sync(0xffffffffu, cm, 8));
        cm = fmaxf(cm, __shfl_xor_sync(0xffffffffu, cm, 16));
        if (cm > m) {                      // warp-uniform branch
            const float r = __expf(m - cm);   // exp(-inf)=0 on first hit
            acc.x *= r; acc.y *= r; acc.z *= r; acc.w *= r;
            Zp *= r;
            m = cm;
        }

        const float w = __expf(s - m);
        if (l4 == 0) Zp += w;              // each key counted once

        // route weights to value lanes
        const float w0 = __shfl_sync(0xffffffffu, w, wsrc0);
        const float w1 = __shfl_sync(0xffffffffu, w, wsrc1);

        // ---- accumulate 8 value rows (2 dense 512B loads/warp) ----
        const float4 v0 = __ldcs(reinterpret_cast<const float4*>(
                               vb + (size_t)(k0 + vk) * C + cq));
        const float4 v1 = __ldcs(reinterpret_cast<const float4*>(
                               vb + (size_t)(k0 + 4 + vk) * C + cq));
        acc.x = fmaf(w0, v0.x, fmaf(w1, v1.x, acc.x));
        acc.y = fmaf(w0, v0.y, fmaf(w1, v1.y, acc.y));
        acc.z = fmaf(w0, v0.z, fmaf(w1, v1.z, acc.z));
        acc.w = fmaf(w0, v0.w, fmaf(w1, v1.w, acc.w));
    }

    // ---- intra-warp reduce: acc over key slots (lane bits 3,4) ----
    acc.x += __shfl_xor_sync(0xffffffffu, acc.x, 8);
    acc.y += __shfl_xor_sync(0xffffffffu, acc.y, 8);
    acc.z += __shfl_xor_sync(0xffffffffu, acc.z, 8);
    acc.w += __shfl_xor_sync(0xffffffffu, acc.w, 8);
    acc.x += __shfl_xor_sync(0xffffffffu, acc.x, 16);
    acc.y += __shfl_xor_sync(0xffffffffu, acc.y, 16);
    acc.z += __shfl_xor_sync(0xffffffffu, acc.z, 16);
    acc.w += __shfl_xor_sync(0xffffffffu, acc.w, 16);

    // Z: full warp reduce (contributions only on l4==0 lanes)
    #pragma unroll
    for (int o = 16; o; o >>= 1)
        Zp += __shfl_xor_sync(0xffffffffu, Zp, o);

    if (lane < 8)
        *reinterpret_cast<float4*>(&s_acc[warp][cq]) = acc;  // 16B aligned
    if (lane == 0) { s_m[warp] = m; s_zz[warp] = Zp; }
    __syncthreads();

    // ---- cross-warp merge with max-rescale ----
    if (tid < C) {
        float M = s_m[0];
        #pragma unroll
        for (int w = 1; w < NW; w++) M = fmaxf(M, s_m[w]);
        float num = 0.f, den = 0.f;
        #pragma unroll
        for (int w = 0; w < NW; w++) {
            const float f = __expf(s_m[w] - M);
            num = fmaf(f, s_acc[w][tid], num);
            den = fmaf(f, s_zz[w], den);
        }
        out[(size_t)b * C + tid] = num / den;
    }
}

extern "C" void kernel_launch(void* const* d_in, const int* in_sizes, int n_in,
                              void* d_out, int out_size)
{
    const float* x      = (const float*)d_in[0];
    const float* keys   = (const float*)d_in[1];
    const float* values = (const float*)d_in[2];
    const float* gamma  = (const float*)d_in[3];
    float* out = (float*)d_out;

    const int B = in_sizes[0] / D;     // 2048
    nw_attn_fused<<<B, NT>>>(x, keys, values, gamma, out);
}